// round 2
// baseline (speedup 1.0000x reference)
#include <cuda_runtime.h>
#include <math.h>

// Problem constants: B=1, C=256, H=W=96
#define C_DIM 256
#define HDIM  96
#define HW    9216          // H*W
#define CW    24576         // C*W
#define NPIX  (C_DIM*HW)    // 2359296

// Scratch (device globals; no allocation allowed)
__device__ float g_FQ[NPIX];    // frequency-filtered map (input to Q conv)
__device__ float g_FQM[CW];     // Fuse_Q_mask: max over 96 strided rows of Q

// ---------------------------------------------------------------------------
__global__ void init_fqm_kernel() {
    int i = blockIdx.x * blockDim.x + threadIdx.x;
    if (i < CW) g_FQM[i] = -INFINITY;
}

// ---------------------------------------------------------------------------
// Per-channel: a=|x|, q=floor(255*(a-min)/ptp), keep DFT freqs kr,kc in
// {-2,-1,0,1} (the fftshift-centered 4x4 box), inverse-synthesize, abs.
// One block per channel, 256 threads. Channel staged in smem (36 KB).
__global__ __launch_bounds__(256) void freq_kernel(const float* __restrict__ x) {
    __shared__ float sa[HW];          // 36864 B
    __shared__ float twc[96], tws[96];
    __shared__ float sF[32];          // 16 complex coefficients (re,im)
    __shared__ float sP[4 * 96 * 2];  // column partials P[kr][w]
    __shared__ float sWarp[8][32];
    __shared__ float sMin[8], sMax[8];

    const int c   = blockIdx.x;
    const int tid = threadIdx.x;
    const float* xc = x + c * HW;

    float lmin = INFINITY, lmax = -INFINITY;
    for (int i = tid; i < HW; i += 256) {
        float a = fabsf(xc[i]);
        sa[i] = a;
        lmin = fminf(lmin, a);
        lmax = fmaxf(lmax, a);
    }
    #pragma unroll
    for (int off = 16; off; off >>= 1) {
        lmin = fminf(lmin, __shfl_down_sync(0xffffffffu, lmin, off));
        lmax = fmaxf(lmax, __shfl_down_sync(0xffffffffu, lmax, off));
    }
    const int wid = tid >> 5, lane = tid & 31;
    if (lane == 0) { sMin[wid] = lmin; sMax[wid] = lmax; }
    if (tid < 96) {  // twiddle table, fp64 trig -> correctly rounded fp32
        double th = 2.0 * 3.14159265358979323846 * (double)tid / 96.0;
        twc[tid] = (float)cos(th);
        tws[tid] = (float)sin(th);
    }
    __syncthreads();

    float mn = sMin[0], mx = sMax[0];
    #pragma unroll
    for (int j = 1; j < 8; j++) { mn = fminf(mn, sMin[j]); mx = fmaxf(mx, sMax[j]); }
    const float ptp = mx - mn;

    // ---- analysis: 16 complex DFT coefficients --------------------------
    float acc[32];
    #pragma unroll
    for (int j = 0; j < 32; j++) acc[j] = 0.f;

    for (int i = tid; i < HW; i += 256) {
        float q = floorf(__fdiv_rn(255.0f * (sa[i] - mn), ptp));
        int h = i / 96, w = i - h * 96;
        int mr[4], mc[4];
        #pragma unroll
        for (int t = 0; t < 4; t++) {
            mr[t] = ((t - 2) * h + 192) % 96;   // phase index of e^{-2pi i kr h/96}
            mc[t] = ((t - 2) * w + 192) % 96;
        }
        #pragma unroll
        for (int a_ = 0; a_ < 4; a_++)
            #pragma unroll
            for (int b_ = 0; b_ < 4; b_++) {
                int m = mr[a_] + mc[b_]; if (m >= 96) m -= 96;
                int p = a_ * 4 + b_;
                acc[2 * p]     += q * twc[m];   // e^{-i t} = (cos, -sin)
                acc[2 * p + 1] -= q * tws[m];
            }
    }
    #pragma unroll
    for (int j = 0; j < 32; j++)
        #pragma unroll
        for (int off = 16; off; off >>= 1)
            acc[j] += __shfl_down_sync(0xffffffffu, acc[j], off);
    if (lane == 0) {
        #pragma unroll
        for (int j = 0; j < 32; j++) sWarp[wid][j] = acc[j];
    }
    __syncthreads();
    if (tid < 32) {   // deterministic 8-way tree
        float s = 0.f;
        #pragma unroll
        for (int j = 0; j < 8; j++) s += sWarp[j][tid];
        sF[tid] = s;
    }
    __syncthreads();

    // ---- synthesis: column partials, then per-pixel 4-term sum ----------
    if (tid < 96) {
        int w = tid;
        #pragma unroll
        for (int kr = 0; kr < 4; kr++) {
            float pre = 0.f, pim = 0.f;
            #pragma unroll
            for (int kc = 0; kc < 4; kc++) {
                int m = ((kc - 2) * w + 192) % 96;
                float fr = sF[2 * (kr * 4 + kc)], fi = sF[2 * (kr * 4 + kc) + 1];
                float cr = twc[m], si = tws[m];          // e^{+i t}
                pre += fr * cr - fi * si;
                pim += fr * si + fi * cr;
            }
            sP[(kr * 96 + w) * 2]     = pre;
            sP[(kr * 96 + w) * 2 + 1] = pim;
        }
    }
    __syncthreads();

    const float inv = 1.0f / 9216.0f;
    for (int i = tid; i < HW; i += 256) {
        int h = i / 96, w = i - h * 96;
        float re = 0.f, im = 0.f;
        #pragma unroll
        for (int kr = 0; kr < 4; kr++) {
            int mh = ((kr - 2) * h + 192) % 96;
            float cr = twc[mh], si = tws[mh];
            float pre = sP[(kr * 96 + w) * 2], pim = sP[(kr * 96 + w) * 2 + 1];
            re += pre * cr - pim * si;
            im += pre * si + pim * cr;
        }
        g_FQ[c * HW + i] = sqrtf(re * re + im * im) * inv;
    }
}

// ---------------------------------------------------------------------------
__device__ __forceinline__ void atomicMaxFloat(float* addr, float val) {
    if (val >= 0.0f) atomicMax((int*)addr, __float_as_int(val));
    else             atomicMin((unsigned int*)addr, __float_as_uint(val));
}

// SGEMM  out[o,p] = sum_c W[o,c]*X[c,p],  O=256, P=9216, K=256.
// 128x128 tile, BK=16, 256 threads, 8x8 per thread.
// MODE 0 (Q): X = g_FQ, epilogue atomic-max into g_FQM[(o*HW+p)%CW]
// MODE 1 (V): X = fuse, epilogue out = (acc+bias)*(1+g_FQM[...])
template <int MODE>
__global__ __launch_bounds__(256) void gemm_kernel(
    const float* __restrict__ Wm,
    const float* __restrict__ Xin,
    const float* __restrict__ bias,
    float* __restrict__ out)
{
    const float* X = (MODE == 0) ? (const float*)g_FQ : Xin;
    __shared__ float As[16][132];   // +4 pad kills store conflicts
    __shared__ float Bs[16][128];

    const int tid = threadIdx.x;
    const int p0 = blockIdx.x * 128;
    const int o0 = blockIdx.y * 128;
    const int tm = tid >> 4, tn = tid & 15;

    float accv[8][8];
    #pragma unroll
    for (int i = 0; i < 8; i++)
        #pragma unroll
        for (int j = 0; j < 8; j++) accv[i][j] = 0.f;

    for (int k0 = 0; k0 < 256; k0 += 16) {
        #pragma unroll
        for (int it = 0; it < 2; it++) {      // A tile 128x16 (transposed store)
            int row = (tid >> 2) + it * 64;
            int cc  = (tid & 3) * 4;
            float4 v = *(const float4*)(Wm + (o0 + row) * 256 + k0 + cc);
            As[cc + 0][row] = v.x; As[cc + 1][row] = v.y;
            As[cc + 2][row] = v.z; As[cc + 3][row] = v.w;
        }
        #pragma unroll
        for (int it = 0; it < 2; it++) {      // B tile 16x128
            int r  = (tid >> 5) + it * 8;
            int cc = (tid & 31) * 4;
            *(float4*)(&Bs[r][cc]) = *(const float4*)(X + (k0 + r) * HW + p0 + cc);
        }
        __syncthreads();
        #pragma unroll
        for (int kk = 0; kk < 16; kk++) {
            float a[8], b[8];
            *(float4*)(a)     = *(float4*)(&As[kk][tm * 8]);
            *(float4*)(a + 4) = *(float4*)(&As[kk][tm * 8 + 4]);
            *(float4*)(b)     = *(float4*)(&Bs[kk][tn * 8]);
            *(float4*)(b + 4) = *(float4*)(&Bs[kk][tn * 8 + 4]);
            #pragma unroll
            for (int i = 0; i < 8; i++)
                #pragma unroll
                for (int j = 0; j < 8; j++)
                    accv[i][j] += a[i] * b[j];
        }
        __syncthreads();
    }

    #pragma unroll
    for (int i = 0; i < 8; i++) {
        int o = o0 + tm * 8 + i;
        float bo = bias[o];
        #pragma unroll
        for (int j = 0; j < 8; j++) {
            int p = p0 + tn * 8 + j;
            int flat = o * HW + p;
            int idx = flat % CW;
            float val = accv[i][j] + bo;
            if (MODE == 0) {
                atomicMaxFloat(&g_FQM[idx], val);
            } else {
                out[flat] = val * (1.0f + g_FQM[idx]);
            }
        }
    }
}

// ---------------------------------------------------------------------------
extern "C" void kernel_launch(void* const* d_in, const int* in_sizes, int n_in,
                              void* d_out, int out_size) {
    const float* fuse = (const float*)d_in[0];
    const float* Wq   = (const float*)d_in[1];
    const float* bq   = (const float*)d_in[2];
    // d_in[3] (Wk), d_in[4] (bk): dead code — softmax over batch axis of size 1
    const float* Wv   = (const float*)d_in[5];
    const float* bv   = (const float*)d_in[6];
    float* out = (float*)d_out;

    init_fqm_kernel<<<96, 256>>>();
    freq_kernel<<<C_DIM, 256>>>(fuse);
    gemm_kernel<0><<<dim3(72, 2), 256>>>(Wq, nullptr, bq, nullptr);
    gemm_kernel<1><<<dim3(72, 2), 256>>>(Wv, fuse, bv, out);
}

// round 6
// speedup vs baseline: 1.5296x; 1.5296x over previous
#include <cuda_runtime.h>
#include <math.h>
#include <stdint.h>

// Problem constants: B=1, C=256, H=W=96
#define C_DIM 256
#define HDIM  96
#define HW    9216          // H*W
#define CW    24576         // C*W
#define NPIX  (C_DIM*HW)    // 2359296

// Scratch (device globals; no allocation allowed)
__device__ float g_FQ[NPIX];    // frequency-filtered map (input to Q conv)
__device__ float g_FQM[CW];     // Fuse_Q_mask: max over 96 strided rows of Q

// ---------------------------------------------------------------------------
__device__ __forceinline__ void cp_async16(uint32_t dst, const void* src) {
    asm volatile("cp.async.cg.shared.global [%0], [%1], 16;\n" :: "r"(dst), "l"(src));
}
#define CP_ASYNC_COMMIT() asm volatile("cp.async.commit_group;\n")
#define CP_ASYNC_WAIT0()  asm volatile("cp.async.wait_group 0;\n")

__device__ __forceinline__ void atomicMaxFloat(float* addr, float val) {
    if (val >= 0.0f) atomicMax((int*)addr, __float_as_int(val));
    else             atomicMin((unsigned int*)addr, __float_as_uint(val));
}

// ---------------------------------------------------------------------------
// Per-channel frequency filter. Keep DFT freqs kr,kc in {-2,-1,0,1} (the
// fftshift-centered 4x4 box on 96x96), inverse-synthesize, abs, /9216.
// Separable two-stage analysis with precomputed phase-index tables (no mods
// in hot loops). One block per channel, 256 threads.
// Blocks c<96 also initialize g_FQM (folds the old init kernel).
__global__ __launch_bounds__(256) void freq_kernel(const float* __restrict__ x) {
    __shared__ float sa[HW];                  // 36864 B
    __shared__ float twc[96], tws[96];
    __shared__ unsigned char pidx[4][96];     // ((k-2)*v) mod 96
    __shared__ float Gp[2][4][96][2];         // stage1 partials (half,kr,w,re/im)
    __shared__ float sF[32];                  // 16 complex coefficients
    __shared__ float sP[4][96][2];            // synthesis column partials
    __shared__ float sMin[8], sMax[8];

    const int ch  = blockIdx.x;
    const int tid = threadIdx.x;
    const float* xc = x + ch * HW;

    if (ch < 96) g_FQM[ch * 256 + tid] = -INFINITY;   // init Fuse_Q_mask buffer

    if (tid < 96) {  // twiddles, fp64 trig
        double th = 2.0 * 3.14159265358979323846 * (double)tid / 96.0;
        twc[tid] = (float)cos(th);
        tws[tid] = (float)sin(th);
    }
    for (int t = tid; t < 384; t += 256) {    // phase index table
        int k = t / 96, v = t - k * 96;
        int m = ((k - 2) * v) % 96; if (m < 0) m += 96;
        pidx[k][v] = (unsigned char)m;
    }

    float lmin = INFINITY, lmax = -INFINITY;
    for (int i = tid; i < HW; i += 256) {
        float a = fabsf(xc[i]);
        sa[i] = a;
        lmin = fminf(lmin, a);
        lmax = fmaxf(lmax, a);
    }
    #pragma unroll
    for (int off = 16; off; off >>= 1) {
        lmin = fminf(lmin, __shfl_down_sync(0xffffffffu, lmin, off));
        lmax = fmaxf(lmax, __shfl_down_sync(0xffffffffu, lmax, off));
    }
    const int wid = tid >> 5, lane = tid & 31;
    if (lane == 0) { sMin[wid] = lmin; sMax[wid] = lmax; }
    __syncthreads();

    float mn = sMin[0], mx = sMax[0];
    #pragma unroll
    for (int j = 1; j < 8; j++) { mn = fminf(mn, sMin[j]); mx = fmaxf(mx, sMax[j]); }
    const float ptp = mx - mn;

    // ---- stage 1: column DFT over h (4 row-freqs), q computed on the fly --
    if (tid < 192) {
        const int w  = tid >> 1;
        const int h0 = (tid & 1) * 48;
        float gr[4] = {0.f, 0.f, 0.f, 0.f};
        float gi[4] = {0.f, 0.f, 0.f, 0.f};
        for (int j = 0; j < 48; j++) {
            int h = h0 + j;
            float q = floorf(__fdiv_rn(255.0f * (sa[h * 96 + w] - mn), ptp));
            #pragma unroll
            for (int kr = 0; kr < 4; kr++) {
                int m = pidx[kr][h];
                gr[kr] += q * twc[m];   // e^{-i th}: (cos, -sin)
                gi[kr] -= q * tws[m];
            }
        }
        #pragma unroll
        for (int kr = 0; kr < 4; kr++) {
            Gp[tid & 1][kr][w][0] = gr[kr];
            Gp[tid & 1][kr][w][1] = gi[kr];
        }
    }
    __syncthreads();

    // ---- stage 2: 4x4 coefficients ---------------------------------------
    if (tid < 16) {
        int kr = tid >> 2, kc = tid & 3;
        float fr = 0.f, fi = 0.f;
        for (int w = 0; w < 96; w++) {
            float grw = Gp[0][kr][w][0] + Gp[1][kr][w][0];
            float giw = Gp[0][kr][w][1] + Gp[1][kr][w][1];
            int m = pidx[kc][w];
            float cc = twc[m], ss = tws[m];
            fr += grw * cc + giw * ss;      // (grw + i giw) * (cos - i sin)
            fi += giw * cc - grw * ss;
        }
        sF[2 * (kr * 4 + kc)]     = fr;
        sF[2 * (kr * 4 + kc) + 1] = fi;
    }
    __syncthreads();

    // ---- synthesis: column partials over kc ------------------------------
    if (tid < 96) {
        int w = tid;
        #pragma unroll
        for (int kr = 0; kr < 4; kr++) {
            float pre = 0.f, pim = 0.f;
            #pragma unroll
            for (int kc = 0; kc < 4; kc++) {
                int m = pidx[kc][w];
                float fr = sF[2 * (kr * 4 + kc)], fi = sF[2 * (kr * 4 + kc) + 1];
                float cc = twc[m], ss = tws[m];     // e^{+i th}
                pre += fr * cc - fi * ss;
                pim += fr * ss + fi * cc;
            }
            sP[kr][w][0] = pre;
            sP[kr][w][1] = pim;
        }
    }
    __syncthreads();

    // ---- per-pixel 4-term inverse + abs ----------------------------------
    const float inv = 1.0f / 9216.0f;
    for (int i = tid; i < HW; i += 256) {
        int h = i / 96, w = i - h * 96;
        float re = 0.f, im = 0.f;
        #pragma unroll
        for (int kr = 0; kr < 4; kr++) {
            int m = pidx[kr][h];
            float cc = twc[m], ss = tws[m];
            float pre = sP[kr][w][0], pim = sP[kr][w][1];
            re += pre * cc - pim * ss;
            im += pre * ss + pim * cc;
        }
        g_FQ[ch * HW + i] = sqrtf(re * re + im * im) * inv;
    }
}

// ---------------------------------------------------------------------------
// SGEMM  out[o,p] = sum_c W[o,c]*X[c,p],  O=256, P=9216, K=256.
// 128x128 tile, BK=16, 256 threads, 8x8/thread. Double-buffered smem with
// cp.async for B, register-staged transposed A, register double-buffer on kk.
// MODE 0 (Q): X = g_FQ, epilogue tree-max pre-reduction into g_FQM
// MODE 1 (V): X = fuse, epilogue out = (acc+bias)*(1+g_FQM[(o*HW+p)%CW])
template <int MODE>
__global__ __launch_bounds__(256) void gemm_kernel(
    const float* __restrict__ Wm,
    const float* __restrict__ Xin,
    const float* __restrict__ bias,
    float* __restrict__ out)
{
    const float* X = (MODE == 0) ? (const float*)g_FQ : Xin;
    __shared__ float As[2][16][132];     // transposed, +4 pad
    __shared__ float Bs[2][16][128];
    __shared__ float red[16][8][128];    // MODE 0 pre-reduction staging (64KB? no: 16*8*128*4 = 64KB) -- too big
    // NOTE: red overlaps As/Bs lifetime end: see epilogue (uses union below)

    const int tid = threadIdx.x;
    const int p0 = blockIdx.x * 128;
    const int o0 = blockIdx.y * 128;
    const int tm = tid >> 4, tn = tid & 15;

    const int arow = tid >> 2, acol = (tid & 3) * 4;
    const int brow = tid >> 5, bcol = (tid & 31) * 4;

    const float* Aptr = Wm + (o0 + arow) * 256 + acol;
    const float* Bptr = X + brow * HW + p0 + bcol;

    // ---- prologue: tile k0=0 --------------------------------------------
    float4 a0 = *(const float4*)(Aptr);
    float4 a1 = *(const float4*)(Aptr + 64 * 256);
    {
        uint32_t sB = (uint32_t)__cvta_generic_to_shared(&Bs[0][brow][bcol]);
        cp_async16(sB, Bptr);
        cp_async16(sB + 8 * 128 * 4, Bptr + 8 * HW);
        CP_ASYNC_COMMIT();
    }
    As[0][acol + 0][arow] = a0.x; As[0][acol + 1][arow] = a0.y;
    As[0][acol + 2][arow] = a0.z; As[0][acol + 3][arow] = a0.w;
    As[0][acol + 0][arow + 64] = a1.x; As[0][acol + 1][arow + 64] = a1.y;
    As[0][acol + 2][arow + 64] = a1.z; As[0][acol + 3][arow + 64] = a1.w;
    CP_ASYNC_WAIT0();
    __syncthreads();

    float accv[8][8];
    #pragma unroll
    for (int i = 0; i < 8; i++)
        #pragma unroll
        for (int j = 0; j < 8; j++) accv[i][j] = 0.f;

    #pragma unroll 1
    for (int k0i = 0; k0i < 16; k0i++) {
        const int buf = k0i & 1;
        const float* Ab = &As[buf][0][0];
        const float* Bb = &Bs[buf][0][0];

        if (k0i < 15) {   // prefetch next tile
            const float* An = Aptr + (k0i + 1) * 16;
            a0 = *(const float4*)(An);
            a1 = *(const float4*)(An + 64 * 256);
            uint32_t sBn = (uint32_t)__cvta_generic_to_shared(&Bs[buf ^ 1][brow][bcol]);
            const float* Bn = Bptr + (size_t)(k0i + 1) * 16 * HW;
            cp_async16(sBn, Bn);
            cp_async16(sBn + 8 * 128 * 4, Bn + 8 * HW);
            CP_ASYNC_COMMIT();
        }

        float ar[2][8], br[2][8];
        *(float4*)(ar[0])     = *(const float4*)(Ab + tm * 8);
        *(float4*)(ar[0] + 4) = *(const float4*)(Ab + tm * 8 + 4);
        *(float4*)(br[0])     = *(const float4*)(Bb + tn * 8);
        *(float4*)(br[0] + 4) = *(const float4*)(Bb + tn * 8 + 4);

        #pragma unroll
        for (int kk = 0; kk < 16; kk++) {
            const int cur = kk & 1, nx = cur ^ 1;
            if (kk < 15) {
                *(float4*)(ar[nx])     = *(const float4*)(Ab + (kk + 1) * 132 + tm * 8);
                *(float4*)(ar[nx] + 4) = *(const float4*)(Ab + (kk + 1) * 132 + tm * 8 + 4);
                *(float4*)(br[nx])     = *(const float4*)(Bb + (kk + 1) * 128 + tn * 8);
                *(float4*)(br[nx] + 4) = *(const float4*)(Bb + (kk + 1) * 128 + tn * 8 + 4);
            }
            #pragma unroll
            for (int i = 0; i < 8; i++)
                #pragma unroll
                for (int j = 0; j < 8; j++)
                    accv[i][j] += ar[cur][i] * br[cur][j];
        }

        if (k0i < 15) {
            float (*An_)[132] = As[buf ^ 1];
            An_[acol + 0][arow] = a0.x; An_[acol + 1][arow] = a0.y;
            An_[acol + 2][arow] = a0.z; An_[acol + 3][arow] = a0.w;
            An_[acol + 0][arow + 64] = a1.x; An_[acol + 1][arow + 64] = a1.y;
            An_[acol + 2][arow + 64] = a1.z; An_[acol + 3][arow + 64] = a1.w;
            CP_ASYNC_WAIT0();
        }
        __syncthreads();
    }

    // ---- epilogue --------------------------------------------------------
    if (MODE == 0) {
        // Each thread owns rows {o0 + tm*8 + i} and cols {p0 + tn*8 + j}.
        // o0 % 8 == 0, so the row class (o & 7) == i. Stage per-(tm,i) maxes
        // in smem laid out [i][tn*8+j][tm], then tree-reduce over tm.
        // Reuse As+Bs smem region (mainloop done): 8 * 128 * 16 floats = 64KB
        // exceeds static alloc, so reduce in two half-passes of i (4 each).
        float* stage = &As[0][0][0];   // 2*16*132 + 2*16*128 = 8320 floats avail
        #pragma unroll
        for (int half = 0; half < 2; half++) {
            __syncthreads();
            #pragma unroll
            for (int i2 = 0; i2 < 4; i2++) {
                int i = half * 4 + i2;
                float bo = bias[o0 + tm * 8 + i];
                #pragma unroll
                for (int j = 0; j < 8; j++)
                    stage[(i2 * 128 + tn * 8 + j) * 16 + tm] = accv[i][j] + bo;
            }
            __syncthreads();
            // 512 cols per half (4 classes x 128 pcols), 256 threads -> 2 each
            for (int t = tid; t < 512; t += 256) {
                float m = stage[t * 16];
                #pragma unroll
                for (int r = 1; r < 16; r++) m = fmaxf(m, stage[t * 16 + r]);
                int cls = half * 4 + (t >> 7), pcol = t & 127;
                unsigned idx = ((unsigned)cls * 9216u + (unsigned)(p0 + pcol)) % 24576u;
                atomicMaxFloat(&g_FQM[idx], m);
            }
        }
    } else {
        #pragma unroll
        for (int i = 0; i < 8; i++) {
            int o = o0 + tm * 8 + i;
            float bo = bias[o];
            unsigned base = ((unsigned)o * 9216u + (unsigned)(p0 + tn * 8)) % 24576u;
            float m[8];
            #pragma unroll
            for (int j = 0; j < 8; j++) {
                unsigned idx = base + j;
                if (idx >= 24576u) idx -= 24576u;
                m[j] = g_FQM[idx];
            }
            float4 v0, v1;
            v0.x = (accv[i][0] + bo) * (1.0f + m[0]);
            v0.y = (accv[i][1] + bo) * (1.0f + m[1]);
            v0.z = (accv[i][2] + bo) * (1.0f + m[2]);
            v0.w = (accv[i][3] + bo) * (1.0f + m[3]);
            v1.x = (accv[i][4] + bo) * (1.0f + m[4]);
            v1.y = (accv[i][5] + bo) * (1.0f + m[5]);
            v1.z = (accv[i][6] + bo) * (1.0f + m[6]);
            v1.w = (accv[i][7] + bo) * (1.0f + m[7]);
            float* op = out + (size_t)o * HW + p0 + tn * 8;
            *(float4*)(op)     = v0;
            *(float4*)(op + 4) = v1;
        }
    }
}

// ---------------------------------------------------------------------------
extern "C" void kernel_launch(void* const* d_in, const int* in_sizes, int n_in,
                              void* d_out, int out_size) {
    const float* fuse = (const float*)d_in[0];
    const float* Wq   = (const float*)d_in[1];
    const float* bq   = (const float*)d_in[2];
    // d_in[3] (Wk), d_in[4] (bk): dead code — softmax over batch axis of size 1
    const float* Wv   = (const float*)d_in[5];
    const float* bv   = (const float*)d_in[6];
    float* out = (float*)d_out;

    freq_kernel<<<C_DIM, 256>>>(fuse);   // also initializes g_FQM
    gemm_kernel<0><<<dim3(72, 2), 256>>>(Wq, nullptr, bq, nullptr);
    gemm_kernel<1><<<dim3(72, 2), 256>>>(Wv, fuse, bv, out);
}